// round 1
// baseline (speedup 1.0000x reference)
#include <cuda_runtime.h>
#include <math.h>

#define N_NODES 100000
#define N_EDGES 1600000
#define DIN     256
#define DOUT    64
#define K_STEPS 10
#define ALPHA   0.1f

// ---------------- scratch (alloc-free: device globals) ----------------
__device__ float g_h[N_NODES * DOUT];     // relu(xW^T+b)
__device__ float g_zA[N_NODES * DOUT];    // ping
__device__ float g_zB[N_NODES * DOUT];    // pong
__device__ float g_dinv[N_NODES];
__device__ int   g_deg[N_NODES];
__device__ float g_norm[N_EDGES];         // (1-alpha)*dinv[src]*dinv[dst]

// ---------------- degree / norm precompute ----------------
__global__ void deg_init_kernel() {
    int i = blockIdx.x * blockDim.x + threadIdx.x;
    if (i < N_NODES) g_deg[i] = 1;            // self-loop
}

__global__ void deg_count_kernel(const int* __restrict__ dst) {
    int e = blockIdx.x * blockDim.x + threadIdx.x;
    if (e < N_EDGES) atomicAdd(&g_deg[dst[e]], 1);
}

__global__ void dinv_kernel() {
    int i = blockIdx.x * blockDim.x + threadIdx.x;
    if (i < N_NODES) g_dinv[i] = rsqrtf((float)g_deg[i]);
}

__global__ void norm_kernel(const int* __restrict__ src, const int* __restrict__ dst) {
    int e = blockIdx.x * blockDim.x + threadIdx.x;
    if (e < N_EDGES)
        g_norm[e] = (1.0f - ALPHA) * g_dinv[src[e]] * g_dinv[dst[e]];
}

// ---------------- GEMM: h = relu(x @ W^T + b) ----------------
// BM=64 rows, BN=64 (=DOUT), BK=32, 256 threads, 4x4 micro-tiles.
__global__ void gemm_relu_kernel(const float* __restrict__ x,
                                 const float* __restrict__ W,
                                 const float* __restrict__ b) {
    __shared__ float As[64][33];   // x tile  [m][k], pad 33 (odd) -> conflict-free
    __shared__ float Bs[32][68];   // W^T tile [k][n], pad 68 (16B-aligned rows)

    const int tid = threadIdx.x;
    const int rowbase = blockIdx.x * 64;
    const int tx = tid & 15;        // col group (4 cols)
    const int ty = tid >> 4;        // row group (4 rows)

    float acc[4][4];
#pragma unroll
    for (int i = 0; i < 4; i++)
#pragma unroll
        for (int j = 0; j < 4; j++) acc[i][j] = 0.0f;

    for (int kb = 0; kb < DIN; kb += 32) {
        // load x tile: 64x32, coalesced over k
#pragma unroll
        for (int i = 0; i < 8; i++) {
            int m = (tid >> 5) + i * 8;
            int k = tid & 31;
            int r = rowbase + m;
            As[m][k] = (r < N_NODES) ? x[r * DIN + kb + k] : 0.0f;
        }
        // load W tile transposed: Bs[k][n] = W[n][kb+k], coalesced over k
#pragma unroll
        for (int i = 0; i < 8; i++) {
            int n = (tid >> 5) + i * 8;
            int k = tid & 31;
            Bs[k][n] = W[n * DIN + kb + k];
        }
        __syncthreads();

#pragma unroll
        for (int k = 0; k < 32; k++) {
            float a0 = As[ty * 4 + 0][k];
            float a1 = As[ty * 4 + 1][k];
            float a2 = As[ty * 4 + 2][k];
            float a3 = As[ty * 4 + 3][k];
            float4 bv = *(const float4*)&Bs[k][tx * 4];
            acc[0][0] += a0 * bv.x; acc[0][1] += a0 * bv.y; acc[0][2] += a0 * bv.z; acc[0][3] += a0 * bv.w;
            acc[1][0] += a1 * bv.x; acc[1][1] += a1 * bv.y; acc[1][2] += a1 * bv.z; acc[1][3] += a1 * bv.w;
            acc[2][0] += a2 * bv.x; acc[2][1] += a2 * bv.y; acc[2][2] += a2 * bv.z; acc[2][3] += a2 * bv.w;
            acc[3][0] += a3 * bv.x; acc[3][1] += a3 * bv.y; acc[3][2] += a3 * bv.z; acc[3][3] += a3 * bv.w;
        }
        __syncthreads();
    }

    const float4 bb = *(const float4*)&b[tx * 4];
#pragma unroll
    for (int i = 0; i < 4; i++) {
        int r = rowbase + ty * 4 + i;
        if (r < N_NODES) {
            float4 hv;
            hv.x = fmaxf(acc[i][0] + bb.x, 0.0f);
            hv.y = fmaxf(acc[i][1] + bb.y, 0.0f);
            hv.z = fmaxf(acc[i][2] + bb.z, 0.0f);
            hv.w = fmaxf(acc[i][3] + bb.w, 0.0f);
            *(float4*)&g_h[r * DOUT + tx * 4] = hv;
        }
    }
}

// ---------------- propagation step ----------------
// z_out = (1-a)*dinv[i]^2 * z_in + a*h    (self-loop + teleport, fully inits out)
__global__ void init_step_kernel(const float* __restrict__ zin,
                                 float* __restrict__ zout) {
    int idx = blockIdx.x * blockDim.x + threadIdx.x;   // over N*16 float4s
    if (idx < N_NODES * (DOUT / 4)) {
        int node = idx >> 4;
        float di = g_dinv[node];
        float c = (1.0f - ALPHA) * di * di;
        float4 z = ((const float4*)zin)[idx];
        float4 h = ((const float4*)g_h)[idx];
        float4 o;
        o.x = c * z.x + ALPHA * h.x;
        o.y = c * z.y + ALPHA * h.y;
        o.z = c * z.z + ALPHA * h.z;
        o.w = c * z.w + ALPHA * h.w;
        ((float4*)zout)[idx] = o;
    }
}

// z_out[dst] += norm[e] * z_in[src]; 16 threads/edge, float4 per thread
__global__ void scatter_kernel(const int* __restrict__ src,
                               const int* __restrict__ dst,
                               const float* __restrict__ zin,
                               float* __restrict__ zout) {
    int t = blockIdx.x * blockDim.x + threadIdx.x;     // over E*16
    int e = t >> 4;
    int f = t & 15;
    if (e < N_EDGES) {
        int s = src[e];
        int d = dst[e];
        float w = g_norm[e];
        float4 v = ((const float4*)zin)[s * (DOUT / 4) + f];
        float* o = zout + d * DOUT + f * 4;
        atomicAdd(o + 0, w * v.x);
        atomicAdd(o + 1, w * v.y);
        atomicAdd(o + 2, w * v.z);
        atomicAdd(o + 3, w * v.w);
    }
}

// ---------------- launch ----------------
extern "C" void kernel_launch(void* const* d_in, const int* in_sizes, int n_in,
                              void* d_out, int out_size) {
    const float* x  = (const float*)d_in[0];   // [N, DIN]
    const int*   ei = (const int*)d_in[1];     // [2, E]
    const float* W  = (const float*)d_in[2];   // [DOUT, DIN]
    const float* b  = (const float*)d_in[3];   // [DOUT]
    float* out = (float*)d_out;                // [N, DOUT]

    const int* src = ei;
    const int* dst = ei + N_EDGES;

    float *hptr, *zA, *zB;
    cudaGetSymbolAddress((void**)&hptr, g_h);
    cudaGetSymbolAddress((void**)&zA,   g_zA);
    cudaGetSymbolAddress((void**)&zB,   g_zB);

    const int TB = 256;
    // degrees + norms
    deg_init_kernel<<<(N_NODES + TB - 1) / TB, TB>>>();
    deg_count_kernel<<<(N_EDGES + TB - 1) / TB, TB>>>(dst);
    dinv_kernel<<<(N_NODES + TB - 1) / TB, TB>>>();
    norm_kernel<<<(N_EDGES + TB - 1) / TB, TB>>>(src, dst);

    // h = relu(x W^T + b)
    gemm_relu_kernel<<<(N_NODES + 63) / 64, 256>>>(x, W, b);

    // K propagation steps; z^(0) = h; last step writes d_out
    const int initBlocks = (N_NODES * (DOUT / 4) + TB - 1) / TB;
    const int scatBlocks = (N_EDGES * 16 + TB - 1) / TB;

    const float* in = hptr;
    for (int k = 0; k < K_STEPS; k++) {
        float* o = (k == K_STEPS - 1) ? out : ((k & 1) ? zB : zA);
        init_step_kernel<<<initBlocks, TB>>>(in, o);
        scatter_kernel<<<scatBlocks, TB>>>(src, dst, in, o);
        in = o;
    }
}

// round 2
// speedup vs baseline: 4.2299x; 4.2299x over previous
#include <cuda_runtime.h>
#include <math.h>

#define N_NODES 100000
#define N_EDGES 1600000
#define DIN     256
#define DOUT    64
#define K_STEPS 10
#define ALPHA   0.1f

#define SCAN_B   1024
#define NBLK_SCAN ((N_NODES + SCAN_B - 1) / SCAN_B)   // 98

// ---------------- scratch (alloc-free: device globals) ----------------
__device__ float g_h[N_NODES * DOUT];
__device__ float g_zA[N_NODES * DOUT];
__device__ float g_zB[N_NODES * DOUT];
__device__ float g_dinv[N_NODES];
__device__ int   g_indeg[N_NODES];        // in-degree (edges only)
__device__ int   g_cursor[N_NODES];       // fill cursors
__device__ int   g_rowptr[N_NODES + 1];   // CSR row pointers (by dst)
__device__ int   g_csrc[N_EDGES];         // CSR: src node per slot
__device__ float g_cw[N_EDGES];           // CSR: (1-a)*dinv[src]*dinv[dst]
__device__ int   g_bsum[NBLK_SCAN];       // scan block sums
__device__ int   g_boff[NBLK_SCAN];       // scan block offsets

// ---------------- CSR build ----------------
__global__ void zero_kernel() {
    int i = blockIdx.x * blockDim.x + threadIdx.x;
    if (i < N_NODES) { g_indeg[i] = 0; g_cursor[i] = 0; }
}

__global__ void indeg_kernel(const int* __restrict__ dst) {
    int e = blockIdx.x * blockDim.x + threadIdx.x;
    if (e < N_EDGES) atomicAdd(&g_indeg[dst[e]], 1);
}

// hierarchical exclusive scan of g_indeg -> g_rowptr
__global__ void scan1_kernel() {
    __shared__ int sh[SCAN_B];
    int gid = blockIdx.x * SCAN_B + threadIdx.x;
    int v = (gid < N_NODES) ? g_indeg[gid] : 0;
    sh[threadIdx.x] = v;
    __syncthreads();
#pragma unroll
    for (int off = 1; off < SCAN_B; off <<= 1) {
        int t = (threadIdx.x >= off) ? sh[threadIdx.x - off] : 0;
        __syncthreads();
        sh[threadIdx.x] += t;
        __syncthreads();
    }
    if (gid < N_NODES) g_rowptr[gid] = sh[threadIdx.x] - v;   // exclusive, partial
    if (threadIdx.x == SCAN_B - 1) g_bsum[blockIdx.x] = sh[SCAN_B - 1];
}

__global__ void scan2_kernel() {
    if (threadIdx.x == 0) {
        int acc = 0;
        for (int i = 0; i < NBLK_SCAN; i++) { g_boff[i] = acc; acc += g_bsum[i]; }
    }
}

__global__ void scan3_kernel() {
    int gid = blockIdx.x * SCAN_B + threadIdx.x;
    if (gid < N_NODES) g_rowptr[gid] += g_boff[blockIdx.x];
    if (gid == 0) g_rowptr[N_NODES] = N_EDGES;
}

__global__ void dinv_kernel() {
    int i = blockIdx.x * blockDim.x + threadIdx.x;
    if (i < N_NODES) g_dinv[i] = rsqrtf((float)(g_indeg[i] + 1));  // +1 self-loop
}

__global__ void fill_kernel(const int* __restrict__ src, const int* __restrict__ dst) {
    int e = blockIdx.x * blockDim.x + threadIdx.x;
    if (e < N_EDGES) {
        int s = src[e], d = dst[e];
        int pos = g_rowptr[d] + atomicAdd(&g_cursor[d], 1);
        g_csrc[pos] = s;
        g_cw[pos] = (1.0f - ALPHA) * g_dinv[s] * g_dinv[d];
    }
}

// ---------------- GEMM: h = relu(x @ W^T + b) ----------------
__global__ void gemm_relu_kernel(const float* __restrict__ x,
                                 const float* __restrict__ W,
                                 const float* __restrict__ b) {
    __shared__ float As[64][33];
    __shared__ float Bs[32][68];

    const int tid = threadIdx.x;
    const int rowbase = blockIdx.x * 64;
    const int tx = tid & 15;
    const int ty = tid >> 4;

    float acc[4][4];
#pragma unroll
    for (int i = 0; i < 4; i++)
#pragma unroll
        for (int j = 0; j < 4; j++) acc[i][j] = 0.0f;

    for (int kb = 0; kb < DIN; kb += 32) {
#pragma unroll
        for (int i = 0; i < 8; i++) {
            int m = (tid >> 5) + i * 8;
            int k = tid & 31;
            int r = rowbase + m;
            As[m][k] = (r < N_NODES) ? x[r * DIN + kb + k] : 0.0f;
        }
#pragma unroll
        for (int i = 0; i < 8; i++) {
            int n = (tid >> 5) + i * 8;
            int k = tid & 31;
            Bs[k][n] = W[n * DIN + kb + k];
        }
        __syncthreads();

#pragma unroll
        for (int k = 0; k < 32; k++) {
            float a0 = As[ty * 4 + 0][k];
            float a1 = As[ty * 4 + 1][k];
            float a2 = As[ty * 4 + 2][k];
            float a3 = As[ty * 4 + 3][k];
            float4 bv = *(const float4*)&Bs[k][tx * 4];
            acc[0][0] += a0 * bv.x; acc[0][1] += a0 * bv.y; acc[0][2] += a0 * bv.z; acc[0][3] += a0 * bv.w;
            acc[1][0] += a1 * bv.x; acc[1][1] += a1 * bv.y; acc[1][2] += a1 * bv.z; acc[1][3] += a1 * bv.w;
            acc[2][0] += a2 * bv.x; acc[2][1] += a2 * bv.y; acc[2][2] += a2 * bv.z; acc[2][3] += a2 * bv.w;
            acc[3][0] += a3 * bv.x; acc[3][1] += a3 * bv.y; acc[3][2] += a3 * bv.z; acc[3][3] += a3 * bv.w;
        }
        __syncthreads();
    }

    const float4 bb = *(const float4*)&b[tx * 4];
#pragma unroll
    for (int i = 0; i < 4; i++) {
        int r = rowbase + ty * 4 + i;
        if (r < N_NODES) {
            float4 hv;
            hv.x = fmaxf(acc[i][0] + bb.x, 0.0f);
            hv.y = fmaxf(acc[i][1] + bb.y, 0.0f);
            hv.z = fmaxf(acc[i][2] + bb.z, 0.0f);
            hv.w = fmaxf(acc[i][3] + bb.w, 0.0f);
            *(float4*)&g_h[r * DOUT + tx * 4] = hv;
        }
    }
}

// ---------------- fused propagation step (pull / gather, no atomics) ----
// out[i] = (1-a)*dinv[i]^2*z[i] + sum_{e: dst=i} w[e]*z[src[e]] + a*h[i]
// 16 threads per node, one float4 lane each.
__global__ void gather_step_kernel(const float* __restrict__ zin,
                                   float* __restrict__ zout) {
    int t = blockIdx.x * blockDim.x + threadIdx.x;
    int node = t >> 4;
    int f = t & 15;
    if (node >= N_NODES) return;

    const float4* z4 = (const float4*)zin;
    float di = g_dinv[node];
    float c = (1.0f - ALPHA) * di * di;

    float4 zv = z4[node * 16 + f];
    float4 acc;
    acc.x = c * zv.x; acc.y = c * zv.y; acc.z = c * zv.z; acc.w = c * zv.w;

    int j   = g_rowptr[node];
    int end = g_rowptr[node + 1];

    // unroll by 2 for two independent gathers in flight
    for (; j + 1 < end; j += 2) {
        int   s0 = g_csrc[j],   s1 = g_csrc[j + 1];
        float w0 = g_cw[j],     w1 = g_cw[j + 1];
        float4 v0 = z4[s0 * 16 + f];
        float4 v1 = z4[s1 * 16 + f];
        acc.x += w0 * v0.x + w1 * v1.x;
        acc.y += w0 * v0.y + w1 * v1.y;
        acc.z += w0 * v0.z + w1 * v1.z;
        acc.w += w0 * v0.w + w1 * v1.w;
    }
    if (j < end) {
        int s = g_csrc[j];
        float w = g_cw[j];
        float4 v = z4[s * 16 + f];
        acc.x += w * v.x; acc.y += w * v.y; acc.z += w * v.z; acc.w += w * v.w;
    }

    float4 hv = ((const float4*)g_h)[node * 16 + f];
    acc.x += ALPHA * hv.x;
    acc.y += ALPHA * hv.y;
    acc.z += ALPHA * hv.z;
    acc.w += ALPHA * hv.w;

    ((float4*)zout)[node * 16 + f] = acc;
}

// ---------------- launch ----------------
extern "C" void kernel_launch(void* const* d_in, const int* in_sizes, int n_in,
                              void* d_out, int out_size) {
    const float* x  = (const float*)d_in[0];
    const int*   ei = (const int*)d_in[1];
    const float* W  = (const float*)d_in[2];
    const float* b  = (const float*)d_in[3];
    float* out = (float*)d_out;

    const int* src = ei;
    const int* dst = ei + N_EDGES;

    float *hptr, *zA, *zB;
    cudaGetSymbolAddress((void**)&hptr, g_h);
    cudaGetSymbolAddress((void**)&zA,   g_zA);
    cudaGetSymbolAddress((void**)&zB,   g_zB);

    const int TB = 256;
    const int nBlkN = (N_NODES + TB - 1) / TB;
    const int nBlkE = (N_EDGES + TB - 1) / TB;

    // CSR build (by dst) + norms
    zero_kernel<<<nBlkN, TB>>>();
    indeg_kernel<<<nBlkE, TB>>>(dst);
    scan1_kernel<<<NBLK_SCAN, SCAN_B>>>();
    scan2_kernel<<<1, 32>>>();
    scan3_kernel<<<NBLK_SCAN, SCAN_B>>>();
    dinv_kernel<<<nBlkN, TB>>>();
    fill_kernel<<<nBlkE, TB>>>(src, dst);

    // h = relu(x W^T + b)
    gemm_relu_kernel<<<(N_NODES + 63) / 64, 256>>>(x, W, b);

    // K fused propagation steps; z^(0) = h; last step writes d_out
    const int gBlocks = (N_NODES * 16 + TB - 1) / TB;
    const float* in = hptr;
    for (int k = 0; k < K_STEPS; k++) {
        float* o = (k == K_STEPS - 1) ? out : ((k & 1) ? zB : zA);
        gather_step_kernel<<<gBlocks, TB>>>(in, o);
        in = o;
    }
}

// round 3
// speedup vs baseline: 5.0564x; 1.1954x over previous
#include <cuda_runtime.h>
#include <cuda_fp16.h>
#include <math.h>

#define N_NODES 100000
#define N_EDGES 1600000
#define DIN     256
#define DOUT    64
#define K_STEPS 10
#define ALPHA   0.1f

#define SCAN_B   1024
#define NBLK_SCAN ((N_NODES + SCAN_B - 1) / SCAN_B)   // 98

// ---------------- scratch (alloc-free: device globals) ----------------
__device__ float  g_h[N_NODES * DOUT];      // fp32 h (teleport term, exact)
__device__ __half g_h16[N_NODES * DOUT];    // fp16 h (= z^0 for first gather)
__device__ __half g_z16A[N_NODES * DOUT];   // ping (fp16 intermediate z)
__device__ __half g_z16B[N_NODES * DOUT];   // pong
__device__ float  g_dinv[N_NODES];
__device__ int    g_indeg[N_NODES];
__device__ int    g_cursor[N_NODES];
__device__ int    g_rowptr[N_NODES + 1];
__device__ int    g_csrc[N_EDGES];
__device__ float  g_cw[N_EDGES];
__device__ int    g_bsum[NBLK_SCAN];
__device__ int    g_boff[NBLK_SCAN];

// ---------------- CSR build ----------------
__global__ void zero_kernel() {
    int i = blockIdx.x * blockDim.x + threadIdx.x;
    if (i < N_NODES) { g_indeg[i] = 0; g_cursor[i] = 0; }
}

__global__ void indeg_kernel(const int* __restrict__ dst) {
    int e = blockIdx.x * blockDim.x + threadIdx.x;
    if (e < N_EDGES) atomicAdd(&g_indeg[dst[e]], 1);
}

__global__ void scan1_kernel() {
    __shared__ int sh[SCAN_B];
    int gid = blockIdx.x * SCAN_B + threadIdx.x;
    int v = (gid < N_NODES) ? g_indeg[gid] : 0;
    sh[threadIdx.x] = v;
    __syncthreads();
#pragma unroll
    for (int off = 1; off < SCAN_B; off <<= 1) {
        int t = (threadIdx.x >= off) ? sh[threadIdx.x - off] : 0;
        __syncthreads();
        sh[threadIdx.x] += t;
        __syncthreads();
    }
    if (gid < N_NODES) g_rowptr[gid] = sh[threadIdx.x] - v;
    if (threadIdx.x == SCAN_B - 1) g_bsum[blockIdx.x] = sh[SCAN_B - 1];
}

// parallel scan of the 98 block sums (one 128-thread block)
__global__ void scan2_kernel() {
    __shared__ int sh[128];
    int tid = threadIdx.x;
    int v = (tid < NBLK_SCAN) ? g_bsum[tid] : 0;
    sh[tid] = v;
    __syncthreads();
#pragma unroll
    for (int off = 1; off < 128; off <<= 1) {
        int t = (tid >= off) ? sh[tid - off] : 0;
        __syncthreads();
        sh[tid] += t;
        __syncthreads();
    }
    if (tid < NBLK_SCAN) g_boff[tid] = sh[tid] - v;   // exclusive
}

__global__ void scan3_kernel() {
    int gid = blockIdx.x * SCAN_B + threadIdx.x;
    if (gid < N_NODES) g_rowptr[gid] += g_boff[blockIdx.x];
    if (gid == 0) g_rowptr[N_NODES] = N_EDGES;
}

__global__ void dinv_kernel() {
    int i = blockIdx.x * blockDim.x + threadIdx.x;
    if (i < N_NODES) g_dinv[i] = rsqrtf((float)(g_indeg[i] + 1));
}

__global__ void fill_kernel(const int* __restrict__ src, const int* __restrict__ dst) {
    int e = blockIdx.x * blockDim.x + threadIdx.x;
    if (e < N_EDGES) {
        int s = src[e], d = dst[e];
        int pos = g_rowptr[d] + atomicAdd(&g_cursor[d], 1);
        g_csrc[pos] = s;
        g_cw[pos] = (1.0f - ALPHA) * g_dinv[s] * g_dinv[d];
    }
}

// ---------------- GEMM: h = relu(x @ W^T + b); writes fp32 + fp16 ----------
__global__ void gemm_relu_kernel(const float* __restrict__ x,
                                 const float* __restrict__ W,
                                 const float* __restrict__ b) {
    __shared__ float As[64][33];
    __shared__ float Bs[32][68];

    const int tid = threadIdx.x;
    const int rowbase = blockIdx.x * 64;
    const int tx = tid & 15;
    const int ty = tid >> 4;

    float acc[4][4];
#pragma unroll
    for (int i = 0; i < 4; i++)
#pragma unroll
        for (int j = 0; j < 4; j++) acc[i][j] = 0.0f;

    for (int kb = 0; kb < DIN; kb += 32) {
#pragma unroll
        for (int i = 0; i < 8; i++) {
            int m = (tid >> 5) + i * 8;
            int k = tid & 31;
            int r = rowbase + m;
            As[m][k] = (r < N_NODES) ? x[r * DIN + kb + k] : 0.0f;
        }
#pragma unroll
        for (int i = 0; i < 8; i++) {
            int n = (tid >> 5) + i * 8;
            int k = tid & 31;
            Bs[k][n] = W[n * DIN + kb + k];
        }
        __syncthreads();

#pragma unroll
        for (int k = 0; k < 32; k++) {
            float a0 = As[ty * 4 + 0][k];
            float a1 = As[ty * 4 + 1][k];
            float a2 = As[ty * 4 + 2][k];
            float a3 = As[ty * 4 + 3][k];
            float4 bv = *(const float4*)&Bs[k][tx * 4];
            acc[0][0] += a0 * bv.x; acc[0][1] += a0 * bv.y; acc[0][2] += a0 * bv.z; acc[0][3] += a0 * bv.w;
            acc[1][0] += a1 * bv.x; acc[1][1] += a1 * bv.y; acc[1][2] += a1 * bv.z; acc[1][3] += a1 * bv.w;
            acc[2][0] += a2 * bv.x; acc[2][1] += a2 * bv.y; acc[2][2] += a2 * bv.z; acc[2][3] += a2 * bv.w;
            acc[3][0] += a3 * bv.x; acc[3][1] += a3 * bv.y; acc[3][2] += a3 * bv.z; acc[3][3] += a3 * bv.w;
        }
        __syncthreads();
    }

    const float4 bb = *(const float4*)&b[tx * 4];
#pragma unroll
    for (int i = 0; i < 4; i++) {
        int r = rowbase + ty * 4 + i;
        if (r < N_NODES) {
            float4 hv;
            hv.x = fmaxf(acc[i][0] + bb.x, 0.0f);
            hv.y = fmaxf(acc[i][1] + bb.y, 0.0f);
            hv.z = fmaxf(acc[i][2] + bb.z, 0.0f);
            hv.w = fmaxf(acc[i][3] + bb.w, 0.0f);
            *(float4*)&g_h[r * DOUT + tx * 4] = hv;
            __half2 lo = __floats2half2_rn(hv.x, hv.y);
            __half2 hi = __floats2half2_rn(hv.z, hv.w);
            uint2 o;
            o.x = *(unsigned*)&lo;
            o.y = *(unsigned*)&hi;
            *(uint2*)&g_h16[r * DOUT + tx * 4] = o;
        }
    }
}

// ---------------- fused propagation step, fp16 gather, fp32 accumulate ----
// out[i] = (1-a)*dinv[i]^2*z[i] + sum_{e:dst=i} w[e]*z[src[e]] + a*h[i]
// 16 threads/node, each handles 4 features (8B fp16 load per row).
template<int FINAL>
__global__ void gather_step16(const __half* __restrict__ zin,
                              __half* __restrict__ zout,
                              float* __restrict__ fout) {
    int t = blockIdx.x * blockDim.x + threadIdx.x;
    int node = t >> 4;
    int f = t & 15;
    if (node >= N_NODES) return;

    const uint2* z2 = (const uint2*)zin;

    float di = g_dinv[node];
    float c = (1.0f - ALPHA) * di * di;

    uint2 zu = z2[node * 16 + f];
    float2 zl = __half22float2(*(__half2*)&zu.x);
    float2 zh = __half22float2(*(__half2*)&zu.y);
    float a0 = c * zl.x, a1 = c * zl.y, a2 = c * zh.x, a3 = c * zh.y;

    int j   = g_rowptr[node];
    int end = g_rowptr[node + 1];

    for (; j + 3 < end; j += 4) {
        int   s0 = g_csrc[j],     s1 = g_csrc[j + 1];
        int   s2 = g_csrc[j + 2], s3 = g_csrc[j + 3];
        float w0 = g_cw[j],       w1 = g_cw[j + 1];
        float w2 = g_cw[j + 2],   w3 = g_cw[j + 3];
        uint2 u0 = z2[s0 * 16 + f];
        uint2 u1 = z2[s1 * 16 + f];
        uint2 u2 = z2[s2 * 16 + f];
        uint2 u3 = z2[s3 * 16 + f];
        float2 l0 = __half22float2(*(__half2*)&u0.x), h0 = __half22float2(*(__half2*)&u0.y);
        float2 l1 = __half22float2(*(__half2*)&u1.x), h1 = __half22float2(*(__half2*)&u1.y);
        float2 l2 = __half22float2(*(__half2*)&u2.x), h2 = __half22float2(*(__half2*)&u2.y);
        float2 l3 = __half22float2(*(__half2*)&u3.x), h3 = __half22float2(*(__half2*)&u3.y);
        a0 += w0 * l0.x + w1 * l1.x + w2 * l2.x + w3 * l3.x;
        a1 += w0 * l0.y + w1 * l1.y + w2 * l2.y + w3 * l3.y;
        a2 += w0 * h0.x + w1 * h1.x + w2 * h2.x + w3 * h3.x;
        a3 += w0 * h0.y + w1 * h1.y + w2 * h2.y + w3 * h3.y;
    }
    for (; j < end; j++) {
        int s = g_csrc[j];
        float w = g_cw[j];
        uint2 u = z2[s * 16 + f];
        float2 l = __half22float2(*(__half2*)&u.x);
        float2 h = __half22float2(*(__half2*)&u.y);
        a0 += w * l.x; a1 += w * l.y; a2 += w * h.x; a3 += w * h.y;
    }

    float4 hv = ((const float4*)g_h)[node * 16 + f];
    a0 += ALPHA * hv.x;
    a1 += ALPHA * hv.y;
    a2 += ALPHA * hv.z;
    a3 += ALPHA * hv.w;

    if (FINAL) {
        float4 o = make_float4(a0, a1, a2, a3);
        ((float4*)fout)[node * 16 + f] = o;
    } else {
        __half2 lo = __floats2half2_rn(a0, a1);
        __half2 hi = __floats2half2_rn(a2, a3);
        uint2 o;
        o.x = *(unsigned*)&lo;
        o.y = *(unsigned*)&hi;
        ((uint2*)zout)[node * 16 + f] = o;
    }
}

// ---------------- launch ----------------
extern "C" void kernel_launch(void* const* d_in, const int* in_sizes, int n_in,
                              void* d_out, int out_size) {
    const float* x  = (const float*)d_in[0];
    const int*   ei = (const int*)d_in[1];
    const float* W  = (const float*)d_in[2];
    const float* b  = (const float*)d_in[3];
    float* out = (float*)d_out;

    const int* src = ei;
    const int* dst = ei + N_EDGES;

    __half *h16, *zA, *zB;
    cudaGetSymbolAddress((void**)&h16, g_h16);
    cudaGetSymbolAddress((void**)&zA,  g_z16A);
    cudaGetSymbolAddress((void**)&zB,  g_z16B);

    const int TB = 256;
    const int nBlkN = (N_NODES + TB - 1) / TB;
    const int nBlkE = (N_EDGES + TB - 1) / TB;

    // CSR build (by dst) + norms
    zero_kernel<<<nBlkN, TB>>>();
    indeg_kernel<<<nBlkE, TB>>>(dst);
    scan1_kernel<<<NBLK_SCAN, SCAN_B>>>();
    scan2_kernel<<<1, 128>>>();
    scan3_kernel<<<NBLK_SCAN, SCAN_B>>>();
    dinv_kernel<<<nBlkN, TB>>>();
    fill_kernel<<<nBlkE, TB>>>(src, dst);

    // h = relu(x W^T + b), fp32 + fp16 copies
    gemm_relu_kernel<<<(N_NODES + 63) / 64, 256>>>(x, W, b);

    // K propagation steps; z^(0) = h16; final step writes fp32 d_out
    const int gBlocks = (N_NODES * 16 + TB - 1) / TB;
    const __half* in = h16;
    for (int k = 0; k < K_STEPS - 1; k++) {
        __half* o = (k & 1) ? zB : zA;
        gather_step16<0><<<gBlocks, TB>>>(in, o, nullptr);
        in = o;
    }
    gather_step16<1><<<gBlocks, TB>>>(in, nullptr, out);
}

// round 4
// speedup vs baseline: 5.3860x; 1.0652x over previous
#include <cuda_runtime.h>
#include <cuda_fp16.h>
#include <math.h>

#define N_NODES 100000
#define N_EDGES 1600000
#define DIN     256
#define DOUT    64
#define K_STEPS 10
#define ALPHA   0.1f

#define SCAN_B   1024
#define NBLK_SCAN ((N_NODES + SCAN_B - 1) / SCAN_B)   // 98
#define NBINS    64

// ---------------- scratch (alloc-free: device globals) ----------------
__device__ float  g_h[N_NODES * DOUT];      // fp32 h (final-step teleport)
__device__ __half g_h16[N_NODES * DOUT];    // fp16 h (= z^0, per-step teleport)
__device__ __half g_z16A[N_NODES * DOUT];
__device__ __half g_z16B[N_NODES * DOUT];
__device__ float  g_dinv[N_NODES];
__device__ int    g_indeg[N_NODES];
__device__ int    g_cursor[N_NODES];
__device__ int    g_rowptr[N_NODES + 1];
__device__ int2   g_epack[N_EDGES];         // {src, float_bits(w)}
__device__ int    g_bsum[NBLK_SCAN];
__device__ int    g_boff[NBLK_SCAN];
// degree counting sort
__device__ int    g_hist[NBINS];
__device__ int    g_binoff[NBINS];
__device__ int    g_bincur[NBINS];
__device__ int    g_order[N_NODES];

// ---------------- CSR build ----------------
__global__ void zero_kernel() {
    int i = blockIdx.x * blockDim.x + threadIdx.x;
    if (i < N_NODES) { g_indeg[i] = 0; g_cursor[i] = 0; }
    if (i < NBINS)   { g_hist[i] = 0; g_bincur[i] = 0; }
}

__global__ void indeg_kernel(const int* __restrict__ dst) {
    int e = blockIdx.x * blockDim.x + threadIdx.x;
    if (e < N_EDGES) atomicAdd(&g_indeg[dst[e]], 1);
}

__global__ void scan1_kernel() {
    __shared__ int sh[SCAN_B];
    int gid = blockIdx.x * SCAN_B + threadIdx.x;
    int v = (gid < N_NODES) ? g_indeg[gid] : 0;
    sh[threadIdx.x] = v;
    __syncthreads();
#pragma unroll
    for (int off = 1; off < SCAN_B; off <<= 1) {
        int t = (threadIdx.x >= off) ? sh[threadIdx.x - off] : 0;
        __syncthreads();
        sh[threadIdx.x] += t;
        __syncthreads();
    }
    if (gid < N_NODES) g_rowptr[gid] = sh[threadIdx.x] - v;
    if (threadIdx.x == SCAN_B - 1) g_bsum[blockIdx.x] = sh[SCAN_B - 1];
}

__global__ void scan2_kernel() {
    __shared__ int sh[128];
    int tid = threadIdx.x;
    int v = (tid < NBLK_SCAN) ? g_bsum[tid] : 0;
    sh[tid] = v;
    __syncthreads();
#pragma unroll
    for (int off = 1; off < 128; off <<= 1) {
        int t = (tid >= off) ? sh[tid - off] : 0;
        __syncthreads();
        sh[tid] += t;
        __syncthreads();
    }
    if (tid < NBLK_SCAN) g_boff[tid] = sh[tid] - v;
}

__global__ void scan3_kernel() {
    int gid = blockIdx.x * SCAN_B + threadIdx.x;
    if (gid < N_NODES) g_rowptr[gid] += g_boff[blockIdx.x];
    if (gid == 0) g_rowptr[N_NODES] = N_EDGES;
}

__global__ void dinv_kernel() {
    int i = blockIdx.x * blockDim.x + threadIdx.x;
    if (i < N_NODES) g_dinv[i] = rsqrtf((float)(g_indeg[i] + 1));
}

__global__ void fill_kernel(const int* __restrict__ src, const int* __restrict__ dst) {
    int e = blockIdx.x * blockDim.x + threadIdx.x;
    if (e < N_EDGES) {
        int s = src[e], d = dst[e];
        int pos = g_rowptr[d] + atomicAdd(&g_cursor[d], 1);
        float w = (1.0f - ALPHA) * g_dinv[s] * g_dinv[d];
        g_epack[pos] = make_int2(s, __float_as_int(w));
    }
}

// ---------------- degree counting sort -> g_order ----------------
__global__ void hist_kernel() {
    __shared__ int sh[NBINS];
    if (threadIdx.x < NBINS) sh[threadIdx.x] = 0;
    __syncthreads();
    int i = blockIdx.x * blockDim.x + threadIdx.x;
    if (i < N_NODES) atomicAdd(&sh[min(g_indeg[i], NBINS - 1)], 1);
    __syncthreads();
    if (threadIdx.x < NBINS && sh[threadIdx.x])
        atomicAdd(&g_hist[threadIdx.x], sh[threadIdx.x]);
}

__global__ void binscan_kernel() {   // 64 threads
    __shared__ int sh[NBINS];
    int tid = threadIdx.x;
    int v = g_hist[tid];
    sh[tid] = v;
    __syncthreads();
#pragma unroll
    for (int off = 1; off < NBINS; off <<= 1) {
        int t = (tid >= off) ? sh[tid - off] : 0;
        __syncthreads();
        sh[tid] += t;
        __syncthreads();
    }
    g_binoff[tid] = sh[tid] - v;
}

__global__ void order_kernel() {
    int i = blockIdx.x * blockDim.x + threadIdx.x;
    if (i < N_NODES) {
        int bin = min(g_indeg[i], NBINS - 1);
        int pos = g_binoff[bin] + atomicAdd(&g_bincur[bin], 1);
        g_order[pos] = i;
    }
}

// ---------------- GEMM: h = relu(x @ W^T + b); writes fp32 + fp16 ----------
__global__ void gemm_relu_kernel(const float* __restrict__ x,
                                 const float* __restrict__ W,
                                 const float* __restrict__ b) {
    __shared__ float As[64][33];
    __shared__ float Bs[32][68];

    const int tid = threadIdx.x;
    const int rowbase = blockIdx.x * 64;
    const int tx = tid & 15;
    const int ty = tid >> 4;

    float acc[4][4];
#pragma unroll
    for (int i = 0; i < 4; i++)
#pragma unroll
        for (int j = 0; j < 4; j++) acc[i][j] = 0.0f;

    for (int kb = 0; kb < DIN; kb += 32) {
#pragma unroll
        for (int i = 0; i < 8; i++) {
            int m = (tid >> 5) + i * 8;
            int k = tid & 31;
            int r = rowbase + m;
            As[m][k] = (r < N_NODES) ? x[r * DIN + kb + k] : 0.0f;
        }
#pragma unroll
        for (int i = 0; i < 8; i++) {
            int n = (tid >> 5) + i * 8;
            int k = tid & 31;
            Bs[k][n] = W[n * DIN + kb + k];
        }
        __syncthreads();

#pragma unroll
        for (int k = 0; k < 32; k++) {
            float a0 = As[ty * 4 + 0][k];
            float a1 = As[ty * 4 + 1][k];
            float a2 = As[ty * 4 + 2][k];
            float a3 = As[ty * 4 + 3][k];
            float4 bv = *(const float4*)&Bs[k][tx * 4];
            acc[0][0] += a0 * bv.x; acc[0][1] += a0 * bv.y; acc[0][2] += a0 * bv.z; acc[0][3] += a0 * bv.w;
            acc[1][0] += a1 * bv.x; acc[1][1] += a1 * bv.y; acc[1][2] += a1 * bv.z; acc[1][3] += a1 * bv.w;
            acc[2][0] += a2 * bv.x; acc[2][1] += a2 * bv.y; acc[2][2] += a2 * bv.z; acc[2][3] += a2 * bv.w;
            acc[3][0] += a3 * bv.x; acc[3][1] += a3 * bv.y; acc[3][2] += a3 * bv.z; acc[3][3] += a3 * bv.w;
        }
        __syncthreads();
    }

    const float4 bb = *(const float4*)&b[tx * 4];
#pragma unroll
    for (int i = 0; i < 4; i++) {
        int r = rowbase + ty * 4 + i;
        if (r < N_NODES) {
            float4 hv;
            hv.x = fmaxf(acc[i][0] + bb.x, 0.0f);
            hv.y = fmaxf(acc[i][1] + bb.y, 0.0f);
            hv.z = fmaxf(acc[i][2] + bb.z, 0.0f);
            hv.w = fmaxf(acc[i][3] + bb.w, 0.0f);
            *(float4*)&g_h[r * DOUT + tx * 4] = hv;
            __half2 lo = __floats2half2_rn(hv.x, hv.y);
            __half2 hi = __floats2half2_rn(hv.z, hv.w);
            uint2 o;
            o.x = *(unsigned*)&lo;
            o.y = *(unsigned*)&hi;
            *(uint2*)&g_h16[r * DOUT + tx * 4] = o;
        }
    }
}

// ---------------- fused propagation step ----------------
// 8 lanes per node (degree-sorted order), each lane owns 8 features (uint4 of fp16).
__device__ __forceinline__ void acc8(float* acc, float w, uint4 u) {
    __half2* p = (__half2*)&u;
#pragma unroll
    for (int i = 0; i < 4; i++) {
        float2 v = __half22float2(p[i]);
        acc[2 * i]     += w * v.x;
        acc[2 * i + 1] += w * v.y;
    }
}

template<int FINAL>
__global__ void gather_step16(const __half* __restrict__ zin,
                              __half* __restrict__ zout,
                              float* __restrict__ fout) {
    int t = blockIdx.x * blockDim.x + threadIdx.x;
    int slot = t >> 3;
    int f = t & 7;                 // which uint4 (8 features)
    if (slot >= N_NODES) return;
    int node = g_order[slot];

    const uint4* z4 = (const uint4*)zin;

    float di = g_dinv[node];
    float c = (1.0f - ALPHA) * di * di;

    float acc[8];
    {
        uint4 zu = z4[node * 8 + f];
        __half2* p = (__half2*)&zu;
#pragma unroll
        for (int i = 0; i < 4; i++) {
            float2 v = __half22float2(p[i]);
            acc[2 * i]     = c * v.x;
            acc[2 * i + 1] = c * v.y;
        }
    }

    int j   = g_rowptr[node];
    int end = g_rowptr[node + 1];

    // peel to 16B-align the int4 meta loads
    if ((j & 1) && j < end) {
        int2 m = g_epack[j];
        acc8(acc, __int_as_float(m.y), z4[m.x * 8 + f]);
        j++;
    }
    for (; j + 3 < end; j += 4) {
        int4 m01 = *(const int4*)&g_epack[j];
        int4 m23 = *(const int4*)&g_epack[j + 2];
        uint4 v0 = z4[m01.x * 8 + f];
        uint4 v1 = z4[m01.z * 8 + f];
        uint4 v2 = z4[m23.x * 8 + f];
        uint4 v3 = z4[m23.z * 8 + f];
        acc8(acc, __int_as_float(m01.y), v0);
        acc8(acc, __int_as_float(m01.w), v1);
        acc8(acc, __int_as_float(m23.y), v2);
        acc8(acc, __int_as_float(m23.w), v3);
    }
    if (j + 1 < end) {
        int4 m01 = *(const int4*)&g_epack[j];
        acc8(acc, __int_as_float(m01.y), z4[m01.x * 8 + f]);
        acc8(acc, __int_as_float(m01.w), z4[m01.z * 8 + f]);
        j += 2;
    }
    if (j < end) {
        int2 m = g_epack[j];
        acc8(acc, __int_as_float(m.y), z4[m.x * 8 + f]);
    }

    if (FINAL) {
        // fp32 teleport for the final result
        const float4* h4 = (const float4*)g_h;
        float4 ha = h4[node * 16 + 2 * f];
        float4 hb = h4[node * 16 + 2 * f + 1];
        float4 o0 = make_float4(acc[0] + ALPHA * ha.x, acc[1] + ALPHA * ha.y,
                                acc[2] + ALPHA * ha.z, acc[3] + ALPHA * ha.w);
        float4 o1 = make_float4(acc[4] + ALPHA * hb.x, acc[5] + ALPHA * hb.y,
                                acc[6] + ALPHA * hb.z, acc[7] + ALPHA * hb.w);
        float4* fo = (float4*)fout;
        fo[node * 16 + 2 * f]     = o0;
        fo[node * 16 + 2 * f + 1] = o1;
    } else {
        uint4 hu = ((const uint4*)g_h16)[node * 8 + f];
        __half2* p = (__half2*)&hu;
#pragma unroll
        for (int i = 0; i < 4; i++) {
            float2 v = __half22float2(p[i]);
            acc[2 * i]     += ALPHA * v.x;
            acc[2 * i + 1] += ALPHA * v.y;
        }
        uint4 o;
        __half2* q = (__half2*)&o;
#pragma unroll
        for (int i = 0; i < 4; i++)
            q[i] = __floats2half2_rn(acc[2 * i], acc[2 * i + 1]);
        ((uint4*)zout)[node * 8 + f] = o;
    }
}

// ---------------- launch ----------------
extern "C" void kernel_launch(void* const* d_in, const int* in_sizes, int n_in,
                              void* d_out, int out_size) {
    const float* x  = (const float*)d_in[0];
    const int*   ei = (const int*)d_in[1];
    const float* W  = (const float*)d_in[2];
    const float* b  = (const float*)d_in[3];
    float* out = (float*)d_out;

    const int* src = ei;
    const int* dst = ei + N_EDGES;

    __half *h16, *zA, *zB;
    cudaGetSymbolAddress((void**)&h16, g_h16);
    cudaGetSymbolAddress((void**)&zA,  g_z16A);
    cudaGetSymbolAddress((void**)&zB,  g_z16B);

    const int TB = 256;
    const int nBlkN = (N_NODES + TB - 1) / TB;
    const int nBlkE = (N_EDGES + TB - 1) / TB;

    // CSR build (by dst) + norms + degree sort
    zero_kernel<<<nBlkN, TB>>>();
    indeg_kernel<<<nBlkE, TB>>>(dst);
    scan1_kernel<<<NBLK_SCAN, SCAN_B>>>();
    scan2_kernel<<<1, 128>>>();
    scan3_kernel<<<NBLK_SCAN, SCAN_B>>>();
    dinv_kernel<<<nBlkN, TB>>>();
    fill_kernel<<<nBlkE, TB>>>(src, dst);
    hist_kernel<<<nBlkN, TB>>>();
    binscan_kernel<<<1, NBINS>>>();
    order_kernel<<<nBlkN, TB>>>();

    // h = relu(x W^T + b), fp32 + fp16 copies
    gemm_relu_kernel<<<(N_NODES + 63) / 64, 256>>>(x, W, b);

    // K propagation steps; z^(0) = h16; final step writes fp32 d_out
    const int gBlocks = (N_NODES * 8 + TB - 1) / TB;
    const __half* in = h16;
    for (int k = 0; k < K_STEPS - 1; k++) {
        __half* o = (k & 1) ? zB : zA;
        gather_step16<0><<<gBlocks, TB>>>(in, o, nullptr);
        in = o;
    }
    gather_step16<1><<<gBlocks, TB>>>(in, nullptr, out);
}

// round 6
// speedup vs baseline: 6.1270x; 1.1376x over previous
#include <cuda_runtime.h>
#include <cuda_fp16.h>
#include <math.h>

#define N_NODES 100000
#define N_EDGES 1600000
#define DIN     256
#define DOUT    64
#define K_STEPS 10
#define ALPHA   0.1f

#define SCAN_B   1024
#define NBLK_SCAN ((N_NODES + SCAN_B - 1) / SCAN_B)   // 98
#define NBINS    64

// ---------------- scratch (alloc-free: device globals) ----------------
__device__ float  g_h[N_NODES * DOUT];      // fp32 h (final-step teleport)
__device__ __half g_h16[N_NODES * DOUT];    // fp16 h (= z^0, per-step teleport)
__device__ __half g_z16A[N_NODES * DOUT];
__device__ __half g_z16B[N_NODES * DOUT];
__device__ float  g_dinv[N_NODES];
__device__ int    g_indeg[N_NODES];
__device__ int    g_cursor[N_NODES];
__device__ int    g_rowptr[N_NODES + 1];
__device__ int2   g_epack[N_EDGES];         // {src, float_bits(w)}
__device__ int    g_bsum[NBLK_SCAN];
__device__ int    g_boff[NBLK_SCAN];
__device__ int    g_hist[NBINS];
__device__ int    g_binoff[NBINS];
__device__ int    g_bincur[NBINS];
__device__ int    g_order[N_NODES];

// ---------------- CSR build ----------------
__global__ void zero_kernel() {
    int i = blockIdx.x * blockDim.x + threadIdx.x;
    if (i < N_NODES) { g_indeg[i] = 0; g_cursor[i] = 0; }
    if (i < NBINS)   { g_hist[i] = 0; g_bincur[i] = 0; }
}

__global__ void indeg_kernel(const int* __restrict__ dst) {
    int e = blockIdx.x * blockDim.x + threadIdx.x;
    if (e < N_EDGES) atomicAdd(&g_indeg[dst[e]], 1);
}

// scan over indeg + fused degree histogram
__global__ void scan1_kernel() {
    __shared__ int sh[SCAN_B];
    __shared__ int hh[NBINS];
    int gid = blockIdx.x * SCAN_B + threadIdx.x;
    int v = (gid < N_NODES) ? g_indeg[gid] : 0;
    if (threadIdx.x < NBINS) hh[threadIdx.x] = 0;
    sh[threadIdx.x] = v;
    __syncthreads();
    if (gid < N_NODES) atomicAdd(&hh[min(v, NBINS - 1)], 1);
#pragma unroll
    for (int off = 1; off < SCAN_B; off <<= 1) {
        int t = (threadIdx.x >= off) ? sh[threadIdx.x - off] : 0;
        __syncthreads();
        sh[threadIdx.x] += t;
        __syncthreads();
    }
    if (gid < N_NODES) g_rowptr[gid] = sh[threadIdx.x] - v;
    if (threadIdx.x == SCAN_B - 1) g_bsum[blockIdx.x] = sh[SCAN_B - 1];
    if (threadIdx.x < NBINS && hh[threadIdx.x])
        atomicAdd(&g_hist[threadIdx.x], hh[threadIdx.x]);
}

__global__ void scan2_kernel() {
    __shared__ int sh[128];
    int tid = threadIdx.x;
    int v = (tid < NBLK_SCAN) ? g_bsum[tid] : 0;
    sh[tid] = v;
    __syncthreads();
#pragma unroll
    for (int off = 1; off < 128; off <<= 1) {
        int t = (tid >= off) ? sh[tid - off] : 0;
        __syncthreads();
        sh[tid] += t;
        __syncthreads();
    }
    if (tid < NBLK_SCAN) g_boff[tid] = sh[tid] - v;
}

// finalize rowptr + fused dinv
__global__ void scan3_kernel() {
    int gid = blockIdx.x * SCAN_B + threadIdx.x;
    if (gid < N_NODES) {
        g_rowptr[gid] += g_boff[blockIdx.x];
        g_dinv[gid] = rsqrtf((float)(g_indeg[gid] + 1));
    }
    if (gid == 0) g_rowptr[N_NODES] = N_EDGES;
}

__global__ void fill_kernel(const int* __restrict__ src, const int* __restrict__ dst) {
    int e = blockIdx.x * blockDim.x + threadIdx.x;
    if (e < N_EDGES) {
        int s = src[e], d = dst[e];
        int pos = g_rowptr[d] + atomicAdd(&g_cursor[d], 1);
        float w = (1.0f - ALPHA) * g_dinv[s] * g_dinv[d];
        g_epack[pos] = make_int2(s, __float_as_int(w));
    }
}

__global__ void binscan_kernel() {
    __shared__ int sh[NBINS];
    int tid = threadIdx.x;
    int v = g_hist[tid];
    sh[tid] = v;
    __syncthreads();
#pragma unroll
    for (int off = 1; off < NBINS; off <<= 1) {
        int t = (tid >= off) ? sh[tid - off] : 0;
        __syncthreads();
        sh[tid] += t;
        __syncthreads();
    }
    g_binoff[tid] = sh[tid] - v;
}

__global__ void order_kernel() {
    int i = blockIdx.x * blockDim.x + threadIdx.x;
    if (i < N_NODES) {
        int bin = min(g_indeg[i], NBINS - 1);
        int pos = g_binoff[bin] + atomicAdd(&g_bincur[bin], 1);
        g_order[pos] = i;
    }
}

// ---------------- tensor-core GEMM: h = relu(x @ W^T + b) ----------------
// BM=64, BN=64(=DOUT), BK=32. 128 threads = 4 warps; warp w owns rows [w*16, w*16+16).
// mma.sync.m16n8k16 fp16 inputs / fp32 accum; A,B staged in smem as fp16.
__device__ __forceinline__ void mma16816(float* d, const unsigned* a, const unsigned* b) {
    asm volatile(
        "mma.sync.aligned.m16n8k16.row.col.f32.f16.f16.f32 "
        "{%0,%1,%2,%3}, {%4,%5,%6,%7}, {%8,%9}, {%0,%1,%2,%3};\n"
        : "+f"(d[0]), "+f"(d[1]), "+f"(d[2]), "+f"(d[3])
        : "r"(a[0]), "r"(a[1]), "r"(a[2]), "r"(a[3]), "r"(b[0]), "r"(b[1]));
}

__device__ __forceinline__ void ldsm4(unsigned* r, unsigned addr) {
    asm volatile("ldmatrix.sync.aligned.m8n8.x4.shared.b16 {%0,%1,%2,%3}, [%4];\n"
                 : "=r"(r[0]), "=r"(r[1]), "=r"(r[2]), "=r"(r[3]) : "r"(addr));
}

#define APITCH 40   // halfs per row (80B, 16B aligned)

__global__ __launch_bounds__(128, 8)
void gemm_relu_mma(const float* __restrict__ x,
                   const float* __restrict__ W,
                   const float* __restrict__ b) {
    __shared__ __half As[64][APITCH];   // x tile, row-major [m][k]
    __shared__ __half Bs[64][APITCH];   // W tile, [n][k] (k contiguous = col-major B)

    const int tid = threadIdx.x;
    const int lane = tid & 31;
    const int warp = tid >> 5;
    const int rowbase = blockIdx.x * 64;
    const int mw = warp * 16;

    float acc[8][4];
#pragma unroll
    for (int i = 0; i < 8; i++)
#pragma unroll
        for (int j = 0; j < 4; j++) acc[i][j] = 0.0f;

    const unsigned sA = (unsigned)__cvta_generic_to_shared(&As[0][0]);
    const unsigned sB = (unsigned)__cvta_generic_to_shared(&Bs[0][0]);

    // ldmatrix lane addressing (computed once)
    const int mat = lane >> 3;
    const int r8  = lane & 7;
    // A mats: {rows0-7,k0-7},{rows8-15,k0-7},{rows0-7,k8-15},{rows8-15,k8-15}
    const int aRow = mw + r8 + (mat & 1) * 8;
    const int aK   = (mat >> 1) * 8;
    // B mats per 16-n group: {n0-7,k0-7},{n0-7,k8-15},{n8-15,k0-7},{n8-15,k8-15}
    const int bRowOff = r8 + (mat >> 1) * 8;
    const int bK      = (mat & 1) * 8;

    for (int kb = 0; kb < DIN; kb += 32) {
        // stage x -> As (fp32->fp16), 64x32
#pragma unroll
        for (int it = 0; it < 4; it++) {
            int row = (tid >> 3) + it * 16;
            int c4  = (tid & 7) * 4;
            int gr = rowbase + row;
            if (gr < N_NODES) {
                float4 v = *(const float4*)&x[gr * DIN + kb + c4];
                __half2 p01 = __floats2half2_rn(v.x, v.y);
                __half2 p23 = __floats2half2_rn(v.z, v.w);
                *(uint2*)&As[row][c4] = make_uint2(*(unsigned*)&p01, *(unsigned*)&p23);
            }
        }
        // stage W -> Bs, Bs[n][k] = W[n][kb+k], 64x32
#pragma unroll
        for (int it = 0; it < 4; it++) {
            int n  = (tid >> 3) + it * 16;
            int c4 = (tid & 7) * 4;
            float4 v = *(const float4*)&W[n * DIN + kb + c4];
            __half2 p01 = __floats2half2_rn(v.x, v.y);
            __half2 p23 = __floats2half2_rn(v.z, v.w);
            *(uint2*)&Bs[n][c4] = make_uint2(*(unsigned*)&p01, *(unsigned*)&p23);
        }
        __syncthreads();

#pragma unroll
        for (int ks = 0; ks < 2; ks++) {
            const int k0 = ks * 16;
            unsigned a[4];
            ldsm4(a, sA + (unsigned)((aRow * APITCH + k0 + aK) * 2));
            unsigned bfr[16];
#pragma unroll
            for (int p = 0; p < 4; p++) {
                int n0 = p * 16;
                ldsm4(&bfr[p * 4], sB + (unsigned)(((n0 + bRowOff) * APITCH + k0 + bK) * 2));
            }
#pragma unroll
            for (int nt = 0; nt < 8; nt++)
                mma16816(acc[nt], a, &bfr[nt * 2]);
        }
        __syncthreads();
    }

    // epilogue: bias + relu -> g_h (fp32) and g_h16 (fp16)
    const int qr = lane >> 2;          // 0..7
    const int qc = (lane & 3) * 2;     // 0,2,4,6
#pragma unroll
    for (int nt = 0; nt < 8; nt++) {
        int col = nt * 8 + qc;
        float2 bb = *(const float2*)&b[col];
        int r0 = rowbase + mw + qr;
        int r1 = r0 + 8;
        float v00 = fmaxf(acc[nt][0] + bb.x, 0.0f);
        float v01 = fmaxf(acc[nt][1] + bb.y, 0.0f);
        float v10 = fmaxf(acc[nt][2] + bb.x, 0.0f);
        float v11 = fmaxf(acc[nt][3] + bb.y, 0.0f);
        if (r0 < N_NODES) {
            *(float2*)&g_h[r0 * DOUT + col] = make_float2(v00, v01);
            __half2 p = __floats2half2_rn(v00, v01);
            *(unsigned*)&g_h16[r0 * DOUT + col] = *(unsigned*)&p;
        }
        if (r1 < N_NODES) {
            *(float2*)&g_h[r1 * DOUT + col] = make_float2(v10, v11);
            __half2 p = __floats2half2_rn(v10, v11);
            *(unsigned*)&g_h16[r1 * DOUT + col] = *(unsigned*)&p;
        }
    }
}

// ---------------- fused propagation step ----------------
// 8 lanes per node (degree-sorted order), each lane owns 8 features (uint4 of fp16).
__device__ __forceinline__ void acc8(float* acc, float w, uint4 u) {
    __half2* p = (__half2*)&u;
#pragma unroll
    for (int i = 0; i < 4; i++) {
        float2 v = __half22float2(p[i]);
        acc[2 * i]     += w * v.x;
        acc[2 * i + 1] += w * v.y;
    }
}

template<int FINAL>
__global__ void gather_step16(const __half* __restrict__ zin,
                              __half* __restrict__ zout,
                              float* __restrict__ fout) {
    int t = blockIdx.x * blockDim.x + threadIdx.x;
    int slot = t >> 3;
    int f = t & 7;
    if (slot >= N_NODES) return;
    int node = g_order[slot];

    const uint4* z4 = (const uint4*)zin;

    float di = g_dinv[node];
    float c = (1.0f - ALPHA) * di * di;

    float acc[8];
    {
        uint4 zu = z4[node * 8 + f];
        __half2* p = (__half2*)&zu;
#pragma unroll
        for (int i = 0; i < 4; i++) {
            float2 v = __half22float2(p[i]);
            acc[2 * i]     = c * v.x;
            acc[2 * i + 1] = c * v.y;
        }
    }

    int j   = g_rowptr[node];
    int end = g_rowptr[node + 1];

    if ((j & 1) && j < end) {
        int2 m = g_epack[j];
        acc8(acc, __int_as_float(m.y), z4[m.x * 8 + f]);
        j++;
    }
    for (; j + 3 < end; j += 4) {
        int4 m01 = *(const int4*)&g_epack[j];
        int4 m23 = *(const int4*)&g_epack[j + 2];
        uint4 v0 = z4[m01.x * 8 + f];
        uint4 v1 = z4[m01.z * 8 + f];
        uint4 v2 = z4[m23.x * 8 + f];
        uint4 v3 = z4[m23.z * 8 + f];
        acc8(acc, __int_as_float(m01.y), v0);
        acc8(acc, __int_as_float(m01.w), v1);
        acc8(acc, __int_as_float(m23.y), v2);
        acc8(acc, __int_as_float(m23.w), v3);
    }
    if (j + 1 < end) {
        int4 m01 = *(const int4*)&g_epack[j];
        acc8(acc, __int_as_float(m01.y), z4[m01.x * 8 + f]);
        acc8(acc, __int_as_float(m01.w), z4[m01.z * 8 + f]);
        j += 2;
    }
    if (j < end) {
        int2 m = g_epack[j];
        acc8(acc, __int_as_float(m.y), z4[m.x * 8 + f]);
    }

    if (FINAL) {
        const float4* h4 = (const float4*)g_h;
        float4 ha = h4[node * 16 + 2 * f];
        float4 hb = h4[node * 16 + 2 * f + 1];
        float4 o0 = make_float4(acc[0] + ALPHA * ha.x, acc[1] + ALPHA * ha.y,
                                acc[2] + ALPHA * ha.z, acc[3] + ALPHA * ha.w);
        float4 o1 = make_float4(acc[4] + ALPHA * hb.x, acc[5] + ALPHA * hb.y,
                                acc[6] + ALPHA * hb.z, acc[7] + ALPHA * hb.w);
        float4* fo = (float4*)fout;
        fo[node * 16 + 2 * f]     = o0;
        fo[node * 16 + 2 * f + 1] = o1;
    } else {
        uint4 hu = ((const uint4*)g_h16)[node * 8 + f];
        __half2* p = (__half2*)&hu;
#pragma unroll
        for (int i = 0; i < 4; i++) {
            float2 v = __half22float2(p[i]);
            acc[2 * i]     += ALPHA * v.x;
            acc[2 * i + 1] += ALPHA * v.y;
        }
        uint4 o;
        __half2* q = (__half2*)&o;
#pragma unroll
        for (int i = 0; i < 4; i++)
            q[i] = __floats2half2_rn(acc[2 * i], acc[2 * i + 1]);
        ((uint4*)zout)[node * 8 + f] = o;
    }
}

// ---------------- launch ----------------
extern "C" void kernel_launch(void* const* d_in, const int* in_sizes, int n_in,
                              void* d_out, int out_size) {
    const float* x  = (const float*)d_in[0];
    const int*   ei = (const int*)d_in[1];
    const float* W  = (const float*)d_in[2];
    const float* b  = (const float*)d_in[3];
    float* out = (float*)d_out;

    const int* src = ei;
    const int* dst = ei + N_EDGES;

    __half *h16, *zA, *zB;
    cudaGetSymbolAddress((void**)&h16, g_h16);
    cudaGetSymbolAddress((void**)&zA,  g_z16A);
    cudaGetSymbolAddress((void**)&zB,  g_z16B);

    const int TB = 256;
    const int nBlkN = (N_NODES + TB - 1) / TB;
    const int nBlkE = (N_EDGES + TB - 1) / TB;

    // launch order puts gemm at index 3 (the index ncu captures)
    zero_kernel<<<nBlkN, TB>>>();                         // 0
    indeg_kernel<<<nBlkE, TB>>>(dst);                     // 1
    scan1_kernel<<<NBLK_SCAN, SCAN_B>>>();                // 2 (+hist)
    gemm_relu_mma<<<(N_NODES + 63) / 64, 128>>>(x, W, b); // 3 <- profiled
    scan2_kernel<<<1, 128>>>();                           // 4
    scan3_kernel<<<NBLK_SCAN, SCAN_B>>>();                // 5 (+dinv)
    fill_kernel<<<nBlkE, TB>>>(src, dst);                 // 6
    binscan_kernel<<<1, NBINS>>>();                       // 7
    order_kernel<<<nBlkN, TB>>>();                        // 8

    const int gBlocks = (N_NODES * 8 + TB - 1) / TB;
    const __half* in = h16;
    for (int k = 0; k < K_STEPS - 1; k++) {
        __half* o = (k & 1) ? zB : zA;
        gather_step16<0><<<gBlocks, TB>>>(in, o, nullptr);
        in = o;
    }
    gather_step16<1><<<gBlocks, TB>>>(in, nullptr, out);
}

// round 8
// speedup vs baseline: 6.3978x; 1.0442x over previous
#include <cuda_runtime.h>
#include <cuda_fp16.h>
#include <math.h>

#define N_NODES 100000
#define N_EDGES 1600000
#define DIN     256
#define DOUT    64
#define K_STEPS 10
#define ALPHA   0.1f

#define SCAN_B   1024
#define NBLK_SCAN ((N_NODES + SCAN_B - 1) / SCAN_B)   // 98
#define NBINS    64

// ---------------- scratch (alloc-free: device globals) ----------------
__device__ float  g_h[N_NODES * DOUT];      // fp32 h (final-step teleport)
__device__ __half g_h16[N_NODES * DOUT];    // fp16 h (= z^0, per-step teleport)
__device__ __half g_z16A[N_NODES * DOUT];
__device__ __half g_z16B[N_NODES * DOUT];
__device__ float  g_dinv[N_NODES];
__device__ int    g_indeg[N_NODES];
__device__ int    g_cursor[N_NODES];
__device__ int    g_rowptr[N_NODES + 1];
__device__ int2   g_epack[N_EDGES];         // {src, float_bits(w)}
__device__ int    g_bsum[NBLK_SCAN];
__device__ int    g_boff[NBLK_SCAN];
__device__ int    g_hist[NBINS];
__device__ int    g_binoff[NBINS];
__device__ int    g_bincur[NBINS];
__device__ int    g_order[N_NODES];

// ---------------- CSR build ----------------
__global__ void zero_kernel() {
    int i = blockIdx.x * blockDim.x + threadIdx.x;
    if (i < N_NODES) { g_indeg[i] = 0; g_cursor[i] = 0; }
    if (i < NBINS)   { g_hist[i] = 0; g_bincur[i] = 0; }
}

__global__ void indeg_kernel(const int* __restrict__ dst) {
    int e = blockIdx.x * blockDim.x + threadIdx.x;
    if (e < N_EDGES) atomicAdd(&g_indeg[dst[e]], 1);
}

// scan over indeg + fused degree histogram
__global__ void scan1_kernel() {
    __shared__ int sh[SCAN_B];
    __shared__ int hh[NBINS];
    int gid = blockIdx.x * SCAN_B + threadIdx.x;
    int v = (gid < N_NODES) ? g_indeg[gid] : 0;
    if (threadIdx.x < NBINS) hh[threadIdx.x] = 0;
    sh[threadIdx.x] = v;
    __syncthreads();
    if (gid < N_NODES) atomicAdd(&hh[min(v, NBINS - 1)], 1);
#pragma unroll
    for (int off = 1; off < SCAN_B; off <<= 1) {
        int t = (threadIdx.x >= off) ? sh[threadIdx.x - off] : 0;
        __syncthreads();
        sh[threadIdx.x] += t;
        __syncthreads();
    }
    if (gid < N_NODES) g_rowptr[gid] = sh[threadIdx.x] - v;
    if (threadIdx.x == SCAN_B - 1) g_bsum[blockIdx.x] = sh[SCAN_B - 1];
    if (threadIdx.x < NBINS && hh[threadIdx.x])
        atomicAdd(&g_hist[threadIdx.x], hh[threadIdx.x]);
}

__global__ void scan2_kernel() {
    __shared__ int sh[128];
    int tid = threadIdx.x;
    int v = (tid < NBLK_SCAN) ? g_bsum[tid] : 0;
    sh[tid] = v;
    __syncthreads();
#pragma unroll
    for (int off = 1; off < 128; off <<= 1) {
        int t = (tid >= off) ? sh[tid - off] : 0;
        __syncthreads();
        sh[tid] += t;
        __syncthreads();
    }
    if (tid < NBLK_SCAN) g_boff[tid] = sh[tid] - v;
}

// finalize rowptr + fused dinv
__global__ void scan3_kernel() {
    int gid = blockIdx.x * SCAN_B + threadIdx.x;
    if (gid < N_NODES) {
        g_rowptr[gid] += g_boff[blockIdx.x];
        g_dinv[gid] = rsqrtf((float)(g_indeg[gid] + 1));
    }
    if (gid == 0) g_rowptr[N_NODES] = N_EDGES;
}

__global__ void fill_kernel(const int* __restrict__ src, const int* __restrict__ dst) {
    int e = blockIdx.x * blockDim.x + threadIdx.x;
    if (e < N_EDGES) {
        int s = src[e], d = dst[e];
        int pos = g_rowptr[d] + atomicAdd(&g_cursor[d], 1);
        float w = (1.0f - ALPHA) * g_dinv[s] * g_dinv[d];
        g_epack[pos] = make_int2(s, __float_as_int(w));
    }
}

__global__ void binscan_kernel() {
    __shared__ int sh[NBINS];
    int tid = threadIdx.x;
    int v = g_hist[tid];
    sh[tid] = v;
    __syncthreads();
#pragma unroll
    for (int off = 1; off < NBINS; off <<= 1) {
        int t = (tid >= off) ? sh[tid - off] : 0;
        __syncthreads();
        sh[tid] += t;
        __syncthreads();
    }
    g_binoff[tid] = sh[tid] - v;
}

__global__ void order_kernel() {
    int i = blockIdx.x * blockDim.x + threadIdx.x;
    if (i < N_NODES) {
        int bin = min(g_indeg[i], NBINS - 1);
        int pos = g_binoff[bin] + atomicAdd(&g_bincur[bin], 1);
        g_order[pos] = i;
    }
}

// ---------------- tensor-core GEMM: h = relu(x @ W^T + b) ----------------
// BM=64, BN=64(=DOUT), BK=32. 128 threads = 4 warps; warp w owns rows [w*16, w*16+16).
// W (64x256) preloaded fully into smem once; A tile software-pipelined:
// prefetch tile kb+32 LDGs into registers while computing tile kb.
__device__ __forceinline__ void mma16816(float* d, const unsigned* a, const unsigned* b) {
    asm volatile(
        "mma.sync.aligned.m16n8k16.row.col.f32.f16.f16.f32 "
        "{%0,%1,%2,%3}, {%4,%5,%6,%7}, {%8,%9}, {%0,%1,%2,%3};\n"
        : "+f"(d[0]), "+f"(d[1]), "+f"(d[2]), "+f"(d[3])
        : "r"(a[0]), "r"(a[1]), "r"(a[2]), "r"(a[3]), "r"(b[0]), "r"(b[1]));
}

__device__ __forceinline__ void ldsm4(unsigned* r, unsigned addr) {
    asm volatile("ldmatrix.sync.aligned.m8n8.x4.shared.b16 {%0,%1,%2,%3}, [%4];\n"
                 : "=r"(r[0]), "=r"(r[1]), "=r"(r[2]), "=r"(r[3]) : "r"(addr));
}

#define APITCH 40    // halfs per A row  (80B; ldsm conflict-free)
#define WPITCH 264   // halfs per W row (528B; ldsm conflict-free: 132w ≡ 4 mod 32)

__global__ __launch_bounds__(128, 4)
void gemm_relu_mma(const float* __restrict__ x,
                   const float* __restrict__ W,
                   const float* __restrict__ b) {
    __shared__ __half Ws[64][WPITCH];   // full W, [n][k], fp16
    __shared__ __half As[64][APITCH];   // x tile, [m][k0..k0+32)

    const int tid = threadIdx.x;
    const int lane = tid & 31;
    const int warp = tid >> 5;
    const int rowbase = blockIdx.x * 64;
    const int mw = warp * 16;

    // ---- preload entire W into smem (once; W is L2-hot across blocks) ----
#pragma unroll
    for (int it = 0; it < 32; it++) {
        int idx = tid * 4 + it * 512;          // linear over 64*256
        int n = idx >> 8, k = idx & 255;
        float4 v = *(const float4*)&W[idx];
        __half2 p01 = __floats2half2_rn(v.x, v.y);
        __half2 p23 = __floats2half2_rn(v.z, v.w);
        *(uint2*)&Ws[n][k] = make_uint2(*(unsigned*)&p01, *(unsigned*)&p23);
    }

    float acc[8][4];
#pragma unroll
    for (int i = 0; i < 8; i++)
#pragma unroll
        for (int j = 0; j < 4; j++) acc[i][j] = 0.0f;

    const unsigned sA = (unsigned)__cvta_generic_to_shared(&As[0][0]);
    const unsigned sB = (unsigned)__cvta_generic_to_shared(&Ws[0][0]);

    // ldmatrix lane addressing
    const int mat = lane >> 3;
    const int r8  = lane & 7;
    const int aRow = mw + r8 + (mat & 1) * 8;
    const int aK   = (mat >> 1) * 8;
    const int bRowOff = r8 + (mat >> 1) * 8;
    const int bK      = (mat & 1) * 8;

    // A-tile staging addressing: 4 float4 per thread
    const int ar = tid >> 3;            // +it*16 -> row
    const int ac = (tid & 7) * 4;       // k within tile

    // prologue: load tile kb=0 into registers
    float4 pa[4];
#pragma unroll
    for (int it = 0; it < 4; it++) {
        int gr = rowbase + ar + it * 16;
        pa[it] = (gr < N_NODES) ? *(const float4*)&x[gr * DIN + ac]
                                : make_float4(0.f, 0.f, 0.f, 0.f);
    }

    for (int kb = 0; kb < DIN; kb += 32) {
        // store prefetched tile into As
#pragma unroll
        for (int it = 0; it < 4; it++) {
            __half2 p01 = __floats2half2_rn(pa[it].x, pa[it].y);
            __half2 p23 = __floats2half2_rn(pa[it].z, pa[it].w);
            *(uint2*)&As[ar + it * 16][ac] = make_uint2(*(unsigned*)&p01, *(unsigned*)&p23);
        }
        __syncthreads();

        // prefetch next tile (latency hidden behind mma below)
        if (kb + 32 < DIN) {
#pragma unroll
            for (int it = 0; it < 4; it++) {
                int gr = rowbase + ar + it * 16;
                if (gr < N_NODES)
                    pa[it] = *(const float4*)&x[gr * DIN + kb + 32 + ac];
            }
        }

#pragma unroll
        for (int ks = 0; ks < 2; ks++) {
            const int k0 = ks * 16;
            unsigned a[4];
            ldsm4(a, sA + (unsigned)((aRow * APITCH + k0 + aK) * 2));
            unsigned bfr[16];
#pragma unroll
            for (int p = 0; p < 4; p++) {
                int n0 = p * 16;
                ldsm4(&bfr[p * 4],
                      sB + (unsigned)(((n0 + bRowOff) * WPITCH + kb + k0 + bK) * 2));
            }
#pragma unroll
            for (int nt = 0; nt < 8; nt++)
                mma16816(acc[nt], a, &bfr[nt * 2]);
        }
        __syncthreads();
    }

    // epilogue: bias + relu -> g_h (fp32) and g_h16 (fp16)
    const int qr = lane >> 2;
    const int qc = (lane & 3) * 2;
#pragma unroll
    for (int nt = 0; nt < 8; nt++) {
        int col = nt * 8 + qc;
        float2 bb = *(const float2*)&b[col];
        int r0 = rowbase + mw + qr;
        int r1 = r0 + 8;
        float v00 = fmaxf(acc[nt][0] + bb.x, 0.0f);
        float v01 = fmaxf(acc[nt][1] + bb.y, 0.0f);
        float v10 = fmaxf(acc[nt][2] + bb.x, 0.0f);
        float v11 = fmaxf(acc[nt][3] + bb.y, 0.0f);
        if (r0 < N_NODES) {
            *(float2*)&g_h[r0 * DOUT + col] = make_float2(v00, v01);
            __half2 p = __floats2half2_rn(v00, v01);
            *(unsigned*)&g_h16[r0 * DOUT + col] = *(unsigned*)&p;
        }
        if (r1 < N_NODES) {
            *(float2*)&g_h[r1 * DOUT + col] = make_float2(v10, v11);
            __half2 p = __floats2half2_rn(v10, v11);
            *(unsigned*)&g_h16[r1 * DOUT + col] = *(unsigned*)&p;
        }
    }
}

// ---------------- fused propagation step ----------------
// 8 lanes per node (degree-sorted order), each lane owns 8 features (uint4 of fp16).
__device__ __forceinline__ void acc8(float* acc, float w, uint4 u) {
    __half2* p = (__half2*)&u;
#pragma unroll
    for (int i = 0; i < 4; i++) {
        float2 v = __half22float2(p[i]);
        acc[2 * i]     += w * v.x;
        acc[2 * i + 1] += w * v.y;
    }
}

template<int FINAL>
__global__ void gather_step16(const __half* __restrict__ zin,
                              __half* __restrict__ zout,
                              float* __restrict__ fout) {
    int t = blockIdx.x * blockDim.x + threadIdx.x;
    int slot = t >> 3;
    int f = t & 7;
    if (slot >= N_NODES) return;
    int node = g_order[slot];

    const uint4* z4 = (const uint4*)zin;

    float di = g_dinv[node];
    float c = (1.0f - ALPHA) * di * di;

    float acc[8];
    {
        uint4 zu = z4[node * 8 + f];
        __half2* p = (__half2*)&zu;
#pragma unroll
        for (int i = 0; i < 4; i++) {
            float2 v = __half22float2(p[i]);
            acc[2 * i]     = c * v.x;
            acc[2 * i + 1] = c * v.y;
        }
    }

    int j   = g_rowptr[node];
    int end = g_rowptr[node + 1];

    if ((j & 1) && j < end) {
        int2 m = g_epack[j];
        acc8(acc, __int_as_float(m.y), z4[m.x * 8 + f]);
        j++;
    }
    for (; j + 3 < end; j += 4) {
        int4 m01 = *(const int4*)&g_epack[j];
        int4 m23 = *(const int4*)&g_epack[j + 2];
        uint4 v0 = z4[m01.x * 8 + f];
        uint4 v1 = z4[m01.z * 8 + f];
        uint4 v2 = z4[m23.x * 8 + f];
        uint4 v3 = z4[m23.z * 8 + f];
        acc8(acc, __int_as_float(m01.y), v0);
        acc8(acc, __int_as_float(m01.w), v1);
        acc8(acc, __int_as_float(m23.y), v2);
        acc8(acc, __int_as_float(m23.w), v3);
    }
    if (j + 1 < end) {
        int4 m01 = *(const int4*)&g_epack[j];
        acc8(acc, __int_as_float(m01.y), z4[m01.x * 8 + f]);
        acc8(acc, __int_as_float(m01.w), z4[m01.z * 8 + f]);
        j += 2;
    }
    if (j < end) {
        int2 m = g_epack[j];
        acc8(acc, __int_as_float(m.y), z4[m.x * 8 + f]);
    }

    if (FINAL) {
        const float4* h4 = (const float4*)g_h;
        float4 ha = h4[node * 16 + 2 * f];
        float4 hb = h4[node * 16 + 2 * f + 1];
        float4 o0 = make_float4(acc[0] + ALPHA * ha.x, acc[1] + ALPHA * ha.y,
                                acc[2] + ALPHA * ha.z, acc[3] + ALPHA * ha.w);
        float4 o1 = make_float4(acc[4] + ALPHA * hb.x, acc[5] + ALPHA * hb.y,
                                acc[6] + ALPHA * hb.z, acc[7] + ALPHA * hb.w);
        float4* fo = (float4*)fout;
        fo[node * 16 + 2 * f]     = o0;
        fo[node * 16 + 2 * f + 1] = o1;
    } else {
        uint4 hu = ((const uint4*)g_h16)[node * 8 + f];
        __half2* p = (__half2*)&hu;
#pragma unroll
        for (int i = 0; i < 4; i++) {
            float2 v = __half22float2(p[i]);
            acc[2 * i]     += ALPHA * v.x;
            acc[2 * i + 1] += ALPHA * v.y;
        }
        uint4 o;
        __half2* q = (__half2*)&o;
#pragma unroll
        for (int i = 0; i < 4; i++)
            q[i] = __floats2half2_rn(acc[2 * i], acc[2 * i + 1]);
        ((uint4*)zout)[node * 8 + f] = o;
    }
}

// ---------------- launch ----------------
extern "C" void kernel_launch(void* const* d_in, const int* in_sizes, int n_in,
                              void* d_out, int out_size) {
    const float* x  = (const float*)d_in[0];
    const int*   ei = (const int*)d_in[1];
    const float* W  = (const float*)d_in[2];
    const float* b  = (const float*)d_in[3];
    float* out = (float*)d_out;

    const int* src = ei;
    const int* dst = ei + N_EDGES;

    __half *h16, *zA, *zB;
    cudaGetSymbolAddress((void**)&h16, g_h16);
    cudaGetSymbolAddress((void**)&zA,  g_z16A);
    cudaGetSymbolAddress((void**)&zB,  g_z16B);

    const int TB = 256;
    const int nBlkN = (N_NODES + TB - 1) / TB;
    const int nBlkE = (N_EDGES + TB - 1) / TB;

    // launch order keeps gemm at index 3 (the index ncu captures)
    zero_kernel<<<nBlkN, TB>>>();                         // 0
    indeg_kernel<<<nBlkE, TB>>>(dst);                     // 1
    scan1_kernel<<<NBLK_SCAN, SCAN_B>>>();                // 2 (+hist)
    gemm_relu_mma<<<(N_NODES + 63) / 64, 128>>>(x, W, b); // 3 <- profiled
    scan2_kernel<<<1, 128>>>();                           // 4
    scan3_kernel<<<NBLK_SCAN, SCAN_B>>>();                // 5 (+dinv)
    fill_kernel<<<nBlkE, TB>>>(src, dst);                 // 6
    binscan_kernel<<<1, NBINS>>>();                       // 7
    order_kernel<<<nBlkN, TB>>>();                        // 8

    const int gBlocks = (N_NODES * 8 + TB - 1) / TB;
    const __half* in = h16;
    for (int k = 0; k < K_STEPS - 1; k++) {
        __half* o = (k & 1) ? zB : zA;
        gather_step16<0><<<gBlocks, TB>>>(in, o, nullptr);
        in = o;
    }
    gather_step16<1><<<gBlocks, TB>>>(in, nullptr, out);
}